// round 8
// baseline (speedup 1.0000x reference)
#include <cuda_runtime.h>

// Problem constants
#define TOKENS   65536          // 16*64*64
#define DDIM     256
#define KCODES   1024
#define Z_ELEMS  (TOKENS * DDIM)   // 16777216
#define BETA     0.25f
#define EPS_F    1e-5f

// Argmin tiling: CTA = 256 threads (8 warps). Warp w owns tokens w*8..w*8+7
// (all 32 lanes share those 8 tokens -> z loads are warp-uniform broadcasts).
// K-SPLIT: each CTA covers 512 codes (half the codebook); two CTAs per token
// tile merge via deterministic u64 atomicMin on (dist_key, index).
#define TT       64                      // tokens per CTA
#define KHALF    512                     // codes per CTA
#define KC       128                     // codes per chunk
#define DC       32                      // d per smem stage
#define NCHUNK   (KHALF / KC)            // 4
#define DSTAGES  (DDIM / DC)             // 8
#define NSTAGES  (NCHUNK * DSTAGES)      // 32
#define NBLK_A   (2 * TOKENS / TT)       // 2048
#define NBLK_G   (TOKENS / TT)           // 1024 gather blocks

// smem floats: zs 16384 | se2 512 | es 2 stages x 1024 ul2 (32KB)
#define SM_SE2_F  (TT * DDIM)                    // 16384
#define SM_ES_B   ((TT * DDIM + KHALF) * 4)      // 67584 bytes (16B aligned)
#define SMEM_BYTES (SM_ES_B + 2 * (DC / 4) * KC * 16)   // 100352

// Output layout (flattened reference tuple, float32):
//   [0 .. Z_ELEMS) z_q_st | [Z+0..3] commit, codebook, cluster, perplexity
//   [Z+4 .. Z+4+TOKENS) indices as float

// Scratch (device globals: no allocations allowed)
__device__ unsigned long long g_best[TOKENS];   // (dist_key<<32)|index
__device__ int        g_counts[KCODES];
__device__ double     g_partial[NBLK_G];
__device__ float      g_e2[KCODES];
__device__ float      g_z2[TOKENS];
// codebook repacked: [d/4][k], entry = {pack(e[4q],e[4q+1]), pack(e[4q+2],e[4q+3])}
__device__ ulonglong2 g_ctp4[(DDIM / 4) * KCODES];

// ---------------------------------------------------------------------------
// init: reset histogram + argmin cells (graph replays reuse globals)
// ---------------------------------------------------------------------------
__global__ void vq_init_kernel() {
    int i = blockIdx.x * blockDim.x + threadIdx.x;
    if (i < TOKENS) g_best[i] = ~0ull;
    if (i < KCODES) g_counts[i] = 0;
}

// ---------------------------------------------------------------------------
// prep codebook (coalesced): block = 32 codes via padded smem transpose.
// ---------------------------------------------------------------------------
__global__ void __launch_bounds__(256) vq_prep_cb_kernel(const float* __restrict__ cb) {
    __shared__ float ct[32 * 260];
    const int tid = threadIdx.x;
    const int k0  = blockIdx.x * 32;
    const float* cbb = cb + (size_t)k0 * DDIM;
    #pragma unroll
    for (int p = 0; p < 32; p++) {
        int e = tid + p * 256;            // 0..8191
        ct[(e >> 8) * 260 + (e & 255)] = cbb[e];
    }
    __syncthreads();
    if (tid < 32) {
        const float* row = &ct[tid * 260];
        float s = 0.0f;
        #pragma unroll 8
        for (int d = 0; d < DDIM; d++)
            s = __fadd_rn(s, __fmul_rn(row[d], row[d]));
        g_e2[k0 + tid] = s;
    }
    __syncthreads();
    #pragma unroll
    for (int p = 0; p < 8; p++) {
        int idx = tid + p * 256;          // 0..2047
        int dq  = idx >> 5;               // 0..63
        int kk  = idx & 31;
        const float* row = &ct[kk * 260 + dq * 4];
        float2 p01 = make_float2(row[0], row[1]);
        float2 p23 = make_float2(row[2], row[3]);
        ulonglong2 v;
        v.x = *reinterpret_cast<unsigned long long*>(&p01);
        v.y = *reinterpret_cast<unsigned long long*>(&p23);
        g_ctp4[(size_t)dq * KCODES + k0 + kk] = v;
    }
}

// ---------------------------------------------------------------------------
// prep z2: coalesced loads via padded smem transpose, reference sum order.
// ---------------------------------------------------------------------------
__global__ void __launch_bounds__(256) vq_prep_z2_kernel(const float* __restrict__ z) {
    __shared__ float zt[32 * 257];
    const int tid  = threadIdx.x;
    const int tok0 = blockIdx.x * 32;
    const float* zb = z + (size_t)tok0 * DDIM;
    #pragma unroll
    for (int p = 0; p < 32; p++) {
        int e = tid + p * 256;
        zt[(e >> 8) * 257 + (e & 255)] = zb[e];
    }
    __syncthreads();
    if (tid < 32) {
        const float* row = &zt[tid * 257];
        float s = 0.0f;
        #pragma unroll 8
        for (int d = 0; d < DDIM; d++)
            s = __fadd_rn(s, __fmul_rn(row[d], row[d]));
        g_z2[tok0 + tid] = s;
    }
}

// ---------------------------------------------------------------------------
// argmin over a 512-code half. Software-pipelined (eb one dg ahead, za JIT).
// Merge across the two halves via u64 atomicMin (deterministic lexicographic
// (dist_bits, index) minimum == old (dist <, tie: index <) semantics).
// ---------------------------------------------------------------------------
__global__ void __launch_bounds__(256, 2)
vq_argmin(const float* __restrict__ z) {
    extern __shared__ float smem[];
    float*      zs  = smem;
    float*      se2 = smem + SM_SE2_F;
    ulonglong2* es  = reinterpret_cast<ulonglong2*>(
        reinterpret_cast<char*>(smem) + SM_ES_B);

    const int tid   = threadIdx.x;
    const int lane  = tid & 31;
    const int w     = tid >> 5;              // warp 0..7: tokens w*8..w*8+7
    const int tile  = blockIdx.x >> 1;       // token tile
    const int kbase = (blockIdx.x & 1) * KHALF;
    const int tok0  = tile * TT;

    // Load z tile: 4096 float4s, 16 per thread, coalesced.
    {
        const float4* zg  = reinterpret_cast<const float4*>(z);
        float4*       zs4 = reinterpret_cast<float4*>(zs);
        #pragma unroll
        for (int p = 0; p < 16; p++) {
            int idx = tid + p * 256;
            zs4[idx] = zg[(size_t)tok0 * (DDIM / 4) + idx];
        }
    }
    // Stage this half's e2 into smem (512 floats).
    #pragma unroll
    for (int p = 0; p < 2; p++) {
        int idx = tid + p * 256;
        se2[idx] = g_e2[kbase + idx];
    }

    float z2r[8];
    #pragma unroll
    for (int i = 0; i < 8; i++) z2r[i] = g_z2[tok0 + w * 8 + i];

    float best[8];
    int   bidx[8];
    #pragma unroll
    for (int i = 0; i < 8; i++) { best[i] = 3.4e38f; bidx[i] = 0; }

    // stage prefetch: 4 x 16B cp.async per thread (16KB stage = 1024 ul2)
    #define STAGE_LOAD(S, BUF)                                                   \
    do {                                                                         \
        int kc_ = kbase + ((S) >> 3) * KC;                                       \
        int dc_ = ((S) & 7) * DC;                                                \
        _Pragma("unroll")                                                        \
        for (int q = 0; q < 4; q++) {                                            \
            int idx_ = tid + q * 256;          /* 0..1023 */                     \
            int dg_  = idx_ >> 7;              /* 0..7   */                      \
            int c_   = idx_ & 127;             /* 0..127 */                      \
            const ulonglong2* src_ =                                             \
                &g_ctp4[(size_t)((dc_ >> 2) + dg_) * KCODES + kc_ + c_];         \
            unsigned dst_ = (unsigned)__cvta_generic_to_shared(                  \
                &es[(BUF) * 1024 + idx_]);                                       \
            asm volatile("cp.async.cg.shared.global [%0], [%1], 16;\n"           \
                         :: "r"(dst_), "l"(src_));                               \
        }                                                                        \
        asm volatile("cp.async.commit_group;\n" ::: "memory");                   \
    } while (0)

    STAGE_LOAD(0, 0);

    unsigned long long acc[8][4];
    int buf = 0;

    for (int s = 0; s < NSTAGES; s++) {
        if ((s & 7) == 0) {
            #pragma unroll
            for (int i = 0; i < 8; i++)
                #pragma unroll
                for (int j = 0; j < 4; j++) acc[i][j] = 0ull;
        }

        asm volatile("cp.async.wait_group 0;\n" ::: "memory");
        __syncthreads();
        if (s + 1 < NSTAGES) STAGE_LOAD(s + 1, buf ^ 1);

        const int dc = (s & 7) * DC;
        const ulonglong2* ebp = &es[buf * 1024] + lane;   // dg 0 base (+lane)
        const float*      zap = zs + (w * 8) * DDIM + dc; // token 0, dg 0

        ulonglong2 eb[4];
        #pragma unroll
        for (int j = 0; j < 4; j++) eb[j] = ebp[j * 32];

        #pragma unroll
        for (int dg = 0; dg < DC / 4; dg++) {        // 8 iters of 4 d
            ulonglong2 ebn[4];
            if (dg < DC / 4 - 1) {
                const ulonglong2* ebn_p = ebp + (dg + 1) * KC;
                #pragma unroll
                for (int j = 0; j < 4; j++) ebn[j] = ebn_p[j * 32];
            }
            const float* zrow = zap + 4 * dg;
            ulonglong2 za = *reinterpret_cast<const ulonglong2*>(zrow);
            #pragma unroll
            for (int i = 0; i < 8; i++) {
                ulonglong2 zan;
                if (i < 7)
                    zan = *reinterpret_cast<const ulonglong2*>(
                        zrow + (i + 1) * DDIM);
                #pragma unroll
                for (int j = 0; j < 4; j++) {
                    asm volatile("fma.rn.f32x2 %0, %1, %2, %0;"
                                 : "+l"(acc[i][j]) : "l"(za.x), "l"(eb[j].x));
                    asm volatile("fma.rn.f32x2 %0, %1, %2, %0;"
                                 : "+l"(acc[i][j]) : "l"(za.y), "l"(eb[j].y));
                }
                za = zan;
            }
            #pragma unroll
            for (int j = 0; j < 4; j++) eb[j] = ebn[j];
        }
        buf ^= 1;

        if ((s & 7) == 7) {
            int kcl = (s >> 3) * KC;          // local chunk base
            #pragma unroll
            for (int j = 0; j < 4; j++) {
                int kl = kcl + lane + j * 32;
                float e2k = se2[kl];
                #pragma unroll
                for (int i = 0; i < 8; i++) {
                    float lo = __uint_as_float((unsigned)(acc[i][j] & 0xFFFFFFFFull));
                    float hi = __uint_as_float((unsigned)(acc[i][j] >> 32));
                    float ze = __fadd_rn(lo, hi);
                    float dist = __fsub_rn(__fadd_rn(z2r[i], e2k),
                                           __fmul_rn(2.0f, ze));
                    if (dist < best[i]) { best[i] = dist; bidx[i] = kbase + kl; }
                }
            }
        }
    }
    #undef STAGE_LOAD

    // --- full-warp argmin reduce per token, then global atomicMin merge ---
    #pragma unroll
    for (int i = 0; i < 8; i++) {
        float bd = best[i];
        int   bi = bidx[i];
        #pragma unroll
        for (int off = 16; off > 0; off >>= 1) {
            float od = __shfl_down_sync(0xFFFFFFFFu, bd, off);
            int   oi = __shfl_down_sync(0xFFFFFFFFu, bi, off);
            if (od < bd || (od == bd && oi < bi)) { bd = od; bi = oi; }
        }
        if (lane == 0) {
            unsigned b  = __float_as_uint(bd);
            unsigned fk = b ^ (unsigned)(((int)b >> 31) | 0x80000000);
            unsigned long long key =
                ((unsigned long long)fk << 32) | (unsigned)bi;
            atomicMin(&g_best[tok0 + w * 8 + i], key);
        }
    }
}

// ---------------------------------------------------------------------------
// gather: finalize indices, histogram, z_q_st, loss partials (memory-bound).
// ---------------------------------------------------------------------------
__global__ void __launch_bounds__(256)
vq_gather(const float* __restrict__ z, const float* __restrict__ cb,
          float* __restrict__ out) {
    __shared__ int    sfin[TT];
    __shared__ double dred[256];
    const int tid  = threadIdx.x;
    const int tok0 = blockIdx.x * TT;

    if (tid < TT) {
        int gt  = tok0 + tid;
        int idx = (int)(unsigned)(g_best[gt] & 0xFFFFFFFFull);
        sfin[tid] = idx;
        out[Z_ELEMS + 4 + gt] = (float)idx;
        atomicAdd(&g_counts[idx], 1);
    }
    __syncthreads();

    double sacc = 0.0;
    const float4* z4  = reinterpret_cast<const float4*>(z);
    const float4* cb4 = reinterpret_cast<const float4*>(cb);
    float4*       o4  = reinterpret_cast<float4*>(out);
    #pragma unroll
    for (int p = 0; p < 16; p++) {
        int e4 = tid + p * 256;           // 0..4095
        int t  = e4 >> 6;
        int d4 = e4 & 63;
        int idx = sfin[t];
        float4 zq = cb4[(size_t)idx * (DDIM / 4) + d4];
        float4 zz = z4[(size_t)tok0 * (DDIM / 4) + e4];
        float4 o;
        o.x = __fadd_rn(zz.x, __fsub_rn(zq.x, zz.x));
        o.y = __fadd_rn(zz.y, __fsub_rn(zq.y, zz.y));
        o.z = __fadd_rn(zz.z, __fsub_rn(zq.z, zz.z));
        o.w = __fadd_rn(zz.w, __fsub_rn(zq.w, zz.w));
        o4[(size_t)tok0 * (DDIM / 4) + e4] = o;
        float dx = __fsub_rn(zz.x, zq.x);
        float dy = __fsub_rn(zz.y, zq.y);
        float dz = __fsub_rn(zz.z, zq.z);
        float dw = __fsub_rn(zz.w, zq.w);
        sacc += (double)__fmul_rn(dx, dx);
        sacc += (double)__fmul_rn(dy, dy);
        sacc += (double)__fmul_rn(dz, dz);
        sacc += (double)__fmul_rn(dw, dw);
    }
    dred[tid] = sacc;
    __syncthreads();
    for (int stride = 128; stride > 0; stride >>= 1) {
        if (tid < stride) dred[tid] += dred[tid + stride];
        __syncthreads();
    }
    if (tid == 0) g_partial[blockIdx.x] = dred[0];
}

// ---------------------------------------------------------------------------
// finalize (parallel, deterministic fixed-tree reductions in double).
// ---------------------------------------------------------------------------
__global__ void __launch_bounds__(256) vq_finalize(float* __restrict__ out) {
    __shared__ double dr[256];
    __shared__ double hr[256];
    __shared__ int    cr[256];
    const int tid = threadIdx.x;

    double s = 0.0;
    #pragma unroll
    for (int q = 0; q < 4; q++) s += g_partial[tid * 4 + q];
    dr[tid] = s;

    int c = 0;
    #pragma unroll
    for (int q = 0; q < 4; q++) c += g_counts[tid * 4 + q];
    cr[tid] = c;
    __syncthreads();
    for (int st = 128; st > 0; st >>= 1) {
        if (tid < st) { dr[tid] += dr[tid + st]; cr[tid] += cr[tid + st]; }
        __syncthreads();
    }
    float denom = __fadd_rn((float)cr[0], EPS_F);

    double h = 0.0;
    #pragma unroll
    for (int q = 0; q < 4; q++) {
        float p = __fdiv_rn((float)g_counts[tid * 4 + q], denom);
        h += (double)__fmul_rn(p, __logf(__fadd_rn(p, EPS_F)));
    }
    hr[tid] = h;
    __syncthreads();
    for (int st = 128; st > 0; st >>= 1) {
        if (tid < st) hr[tid] += hr[tid + st];
        __syncthreads();
    }

    if (tid == 0) {
        float L = (float)(dr[0] / (double)Z_ELEMS);
        out[Z_ELEMS + 0] = L;                                 // commitment
        out[Z_ELEMS + 1] = L;                                 // codebook
        out[Z_ELEMS + 2] = __fadd_rn(L, __fmul_rn(BETA, L));  // cluster
        out[Z_ELEMS + 3] = __expf(-(float)hr[0]);             // perplexity
    }
}

// ---------------------------------------------------------------------------
extern "C" void kernel_launch(void* const* d_in, const int* in_sizes, int n_in,
                              void* d_out, int out_size) {
    const float* z  = (const float*)d_in[0];   // [65536, 256]
    const float* cb = (const float*)d_in[1];   // [1024, 256]
    float* out = (float*)d_out;

    cudaFuncSetAttribute(vq_argmin, cudaFuncAttributeMaxDynamicSharedMemorySize,
                         SMEM_BYTES);

    vq_init_kernel<<<TOKENS / 256, 256>>>();
    vq_prep_cb_kernel<<<KCODES / 32, 256>>>(cb);
    vq_prep_z2_kernel<<<TOKENS / 32, 256>>>(z);
    vq_argmin<<<NBLK_A, 256, SMEM_BYTES>>>(z);
    vq_gather<<<NBLK_G, 256>>>(z, cb, out);
    vq_finalize<<<1, 256>>>(out);
}

// round 9
// speedup vs baseline: 1.0959x; 1.0959x over previous
#include <cuda_runtime.h>

// Problem constants
#define TOKENS   65536          // 16*64*64
#define DDIM     256
#define KCODES   1024
#define Z_ELEMS  (TOKENS * DDIM)   // 16777216
#define BETA     0.25f
#define EPS_F    1e-5f

// Argmin tiling: CTA = 256 threads (8 warps). Warp w owns tokens w*8..w*8+7
// (all 32 lanes share those 8 tokens -> z loads are warp-uniform broadcasts).
// Lane = code lane: thread covers k = kc + lane + j*32, j = 0..3 (KC=128).
#define TT       64                      // tokens per CTA
#define KC       128                     // codes per chunk
#define DC       32                      // d per smem stage
#define NCHUNK   (KCODES / KC)           // 8
#define DSTAGES  (DDIM / DC)             // 8
#define NSTAGES  (NCHUNK * DSTAGES)      // 64
#define NBLK_A   (TOKENS / TT)           // 1024

// smem floats: zs 16384 | se2 1024 | sz2 64 | es 2 stages x 1024 ul2 (32KB)
#define SM_SE2_F  (TT * DDIM)                        // 16384
#define SM_SZ2_F  (TT * DDIM + KCODES)               // 17408
#define SM_ES_B   ((TT * DDIM + KCODES + TT) * 4)    // 69888 bytes (16B aligned)
#define SMEM_BYTES (SM_ES_B + 2 * (DC / 4) * KC * 16)   // 102656

// Output layout (flattened reference tuple, float32):
//   [0 .. Z_ELEMS) z_q_st | [Z+0..3] commit, codebook, cluster, perplexity
//   [Z+4 .. Z+4+TOKENS) indices as float

// Scratch (device globals: no allocations allowed)
__device__ int        g_counts[KCODES];
__device__ double     g_partial[NBLK_A];
__device__ float      g_e2[KCODES];
__device__ float      g_z2[TOKENS];
// codebook repacked: [d/4][k], entry = {pack(e[4q],e[4q+1]), pack(e[4q+2],e[4q+3])}
__device__ ulonglong2 g_ctp4[(DDIM / 4) * KCODES];

// ---------------------------------------------------------------------------
__global__ void vq_init_kernel() {
    int i = blockIdx.x * blockDim.x + threadIdx.x;
    if (i < KCODES) g_counts[i] = 0;
}

// ---------------------------------------------------------------------------
// prep codebook (coalesced): block = 32 codes via padded smem transpose.
// ---------------------------------------------------------------------------
__global__ void __launch_bounds__(256) vq_prep_cb_kernel(const float* __restrict__ cb) {
    __shared__ float ct[32 * 260];
    const int tid = threadIdx.x;
    const int k0  = blockIdx.x * 32;
    const float* cbb = cb + (size_t)k0 * DDIM;
    #pragma unroll
    for (int p = 0; p < 32; p++) {
        int e = tid + p * 256;            // 0..8191
        ct[(e >> 8) * 260 + (e & 255)] = cbb[e];
    }
    __syncthreads();
    if (tid < 32) {
        const float* row = &ct[tid * 260];
        float s = 0.0f;
        #pragma unroll 8
        for (int d = 0; d < DDIM; d++)
            s = __fadd_rn(s, __fmul_rn(row[d], row[d]));
        g_e2[k0 + tid] = s;
    }
    __syncthreads();
    #pragma unroll
    for (int p = 0; p < 8; p++) {
        int idx = tid + p * 256;          // 0..2047
        int dq  = idx >> 5;               // 0..63
        int kk  = idx & 31;
        const float* row = &ct[kk * 260 + dq * 4];
        float2 p01 = make_float2(row[0], row[1]);
        float2 p23 = make_float2(row[2], row[3]);
        ulonglong2 v;
        v.x = *reinterpret_cast<unsigned long long*>(&p01);
        v.y = *reinterpret_cast<unsigned long long*>(&p23);
        g_ctp4[(size_t)dq * KCODES + k0 + kk] = v;
    }
}

// ---------------------------------------------------------------------------
// prep z2: coalesced loads via padded smem transpose, reference sum order.
// ---------------------------------------------------------------------------
__global__ void __launch_bounds__(256) vq_prep_z2_kernel(const float* __restrict__ z) {
    __shared__ float zt[32 * 257];
    const int tid  = threadIdx.x;
    const int tok0 = blockIdx.x * 32;
    const float* zb = z + (size_t)tok0 * DDIM;
    #pragma unroll
    for (int p = 0; p < 32; p++) {
        int e = tid + p * 256;
        zt[(e >> 8) * 257 + (e & 255)] = zb[e];
    }
    __syncthreads();
    if (tid < 32) {
        const float* row = &zt[tid * 257];
        float s = 0.0f;
        #pragma unroll 8
        for (int d = 0; d < DDIM; d++)
            s = __fadd_rn(s, __fmul_rn(row[d], row[d]));
        g_z2[tok0 + tid] = s;
    }
}

// ---------------------------------------------------------------------------
// fused argmin + gather + loss. Mainloop per stage: flat 64-entry token
// pipeline (8 dg x 8 tokens) with za prefetched at DISTANCE 2 (32 issue
// cycles > 29-cycle LDS latency), eb loaded once per dg.
// ---------------------------------------------------------------------------
__global__ void __launch_bounds__(256, 2)
vq_argmin(const float* __restrict__ z, const float* __restrict__ cb,
          float* __restrict__ out) {
    extern __shared__ float smem[];
    float*      zs  = smem;
    float*      se2 = smem + SM_SE2_F;
    float*      sz2 = smem + SM_SZ2_F;
    ulonglong2* es  = reinterpret_cast<ulonglong2*>(
        reinterpret_cast<char*>(smem) + SM_ES_B);

    const int tid  = threadIdx.x;
    const int lane = tid & 31;
    const int w    = tid >> 5;          // warp 0..7: owns tokens w*8..w*8+7
    const int tok0 = blockIdx.x * TT;

    // Load z tile: 4096 float4s, 16 per thread, coalesced.
    {
        const float4* zg  = reinterpret_cast<const float4*>(z);
        float4*       zs4 = reinterpret_cast<float4*>(zs);
        #pragma unroll
        for (int p = 0; p < 16; p++) {
            int idx = tid + p * 256;
            zs4[idx] = zg[(size_t)tok0 * (DDIM / 4) + idx];
        }
    }
    // Stage e2 and z2 into smem.
    #pragma unroll
    for (int p = 0; p < 4; p++) {
        int idx = tid + p * 256;
        se2[idx] = g_e2[idx];
    }
    if (tid < TT) sz2[tid] = g_z2[tok0 + tid];

    float best[8];
    int   bidx[8];
    #pragma unroll
    for (int i = 0; i < 8; i++) { best[i] = 3.4e38f; bidx[i] = 0; }

    // stage prefetch: 4 x 16B cp.async per thread (16KB stage = 1024 ul2)
    #define STAGE_LOAD(S, BUF)                                                   \
    do {                                                                         \
        int kc_ = ((S) >> 3) * KC;                                               \
        int dc_ = ((S) & 7) * DC;                                                \
        _Pragma("unroll")                                                        \
        for (int q = 0; q < 4; q++) {                                            \
            int idx_ = tid + q * 256;          /* 0..1023 */                     \
            int dg_  = idx_ >> 7;              /* 0..7   */                      \
            int c_   = idx_ & 127;             /* 0..127 */                      \
            const ulonglong2* src_ =                                             \
                &g_ctp4[(size_t)((dc_ >> 2) + dg_) * KCODES + kc_ + c_];         \
            unsigned dst_ = (unsigned)__cvta_generic_to_shared(                  \
                &es[(BUF) * 1024 + idx_]);                                       \
            asm volatile("cp.async.cg.shared.global [%0], [%1], 16;\n"           \
                         :: "r"(dst_), "l"(src_));                               \
        }                                                                        \
        asm volatile("cp.async.commit_group;\n" ::: "memory");                   \
    } while (0)

    STAGE_LOAD(0, 0);

    unsigned long long acc[8][4];
    int buf = 0;

    for (int s = 0; s < NSTAGES; s++) {
        if ((s & 7) == 0) {
            #pragma unroll
            for (int i = 0; i < 8; i++)
                #pragma unroll
                for (int j = 0; j < 4; j++) acc[i][j] = 0ull;
        }

        asm volatile("cp.async.wait_group 0;\n" ::: "memory");
        __syncthreads();
        if (s + 1 < NSTAGES) STAGE_LOAD(s + 1, buf ^ 1);

        const int dc = (s & 7) * DC;
        const ulonglong2* ebp = &es[buf * 1024] + lane;   // +lane base
        const float*      zap = zs + (w * 8) * DDIM + dc; // token 0, dg 0

        ulonglong2 eb[4];
        #pragma unroll
        for (int j = 0; j < 4; j++) eb[j] = ebp[j * 32];  // dg 0

        // za ring: distance-2 prefetch across the flat 64-token stream
        ulonglong2 zaA = *reinterpret_cast<const ulonglong2*>(zap);          // t=0
        ulonglong2 zaB = *reinterpret_cast<const ulonglong2*>(zap + DDIM);   // t=1

        #pragma unroll
        for (int t = 0; t < 64; t++) {
            const int dg = t >> 3;
            const int i  = t & 7;
            if (i == 0 && dg > 0) {
                // new dg: reload eb (za pipeline keeps FMAs flowing meanwhile)
                #pragma unroll
                for (int j = 0; j < 4; j++) eb[j] = ebp[dg * KC + j * 32];
            }
            ulonglong2 zaC;
            if (t < 62) {
                const int t2  = t + 2;
                const int dg2 = t2 >> 3;
                const int i2  = t2 & 7;
                zaC = *reinterpret_cast<const ulonglong2*>(
                    zap + i2 * DDIM + 4 * dg2);
            }
            #pragma unroll
            for (int j = 0; j < 4; j++) {
                asm volatile("fma.rn.f32x2 %0, %1, %2, %0;"
                             : "+l"(acc[i][j]) : "l"(zaA.x), "l"(eb[j].x));
                asm volatile("fma.rn.f32x2 %0, %1, %2, %0;"
                             : "+l"(acc[i][j]) : "l"(zaA.y), "l"(eb[j].y));
            }
            zaA = zaB;
            zaB = zaC;
        }
        buf ^= 1;

        if ((s & 7) == 7) {
            int kc = (s >> 3) * KC;
            #pragma unroll
            for (int i = 0; i < 8; i++) {
                float z2v = sz2[w * 8 + i];
                #pragma unroll
                for (int j = 0; j < 4; j++) {
                    int k = kc + lane + j * 32;
                    float e2k = se2[k];
                    float lo = __uint_as_float((unsigned)(acc[i][j] & 0xFFFFFFFFull));
                    float hi = __uint_as_float((unsigned)(acc[i][j] >> 32));
                    float ze = __fadd_rn(lo, hi);
                    float dist = __fsub_rn(__fadd_rn(z2v, e2k),
                                           __fmul_rn(2.0f, ze));
                    if (dist < best[i]) { best[i] = dist; bidx[i] = k; }
                }
            }
        }
    }
    #undef STAGE_LOAD

    // --- full-warp argmin reduce per token (min dist, min index on ties) ---
    __syncthreads();                       // es region free for reuse
    int*    sfin = reinterpret_cast<int*>(
        reinterpret_cast<char*>(smem) + SM_ES_B);           // 64 ints
    double* dred = reinterpret_cast<double*>(
        reinterpret_cast<char*>(smem) + SM_ES_B + 256);     // 256 doubles

    #pragma unroll
    for (int i = 0; i < 8; i++) {
        float bd = best[i];
        int   bi = bidx[i];
        #pragma unroll
        for (int off = 16; off > 0; off >>= 1) {
            float od = __shfl_down_sync(0xFFFFFFFFu, bd, off);
            int   oi = __shfl_down_sync(0xFFFFFFFFu, bi, off);
            if (od < bd || (od == bd && oi < bi)) { bd = od; bi = oi; }
        }
        if (lane == 0) {
            int t  = w * 8 + i;
            int gt = tok0 + t;
            out[Z_ELEMS + 4 + gt] = (float)bi;
            atomicAdd(&g_counts[bi], 1);
            sfin[t] = bi;
        }
    }
    __syncthreads();

    // --- fused gather + z_q_st write + loss partial (z tile still in smem) ---
    double sacc = 0.0;
    const float4* cb4 = reinterpret_cast<const float4*>(cb);
    const float4* zs4 = reinterpret_cast<const float4*>(zs);
    float4*       o4  = reinterpret_cast<float4*>(out);
    #pragma unroll
    for (int p = 0; p < 16; p++) {
        int e4 = tid + p * 256;           // 0..4095
        int t  = e4 >> 6;
        int d4 = e4 & 63;
        int idx = sfin[t];
        float4 zq = cb4[(size_t)idx * (DDIM / 4) + d4];
        float4 zz = zs4[e4];
        float4 o;
        o.x = __fadd_rn(zz.x, __fsub_rn(zq.x, zz.x));
        o.y = __fadd_rn(zz.y, __fsub_rn(zq.y, zz.y));
        o.z = __fadd_rn(zz.z, __fsub_rn(zq.z, zz.z));
        o.w = __fadd_rn(zz.w, __fsub_rn(zq.w, zz.w));
        o4[(size_t)tok0 * (DDIM / 4) + e4] = o;
        float dx = __fsub_rn(zz.x, zq.x);
        float dy = __fsub_rn(zz.y, zq.y);
        float dz = __fsub_rn(zz.z, zq.z);
        float dw = __fsub_rn(zz.w, zq.w);
        sacc += (double)__fmul_rn(dx, dx);
        sacc += (double)__fmul_rn(dy, dy);
        sacc += (double)__fmul_rn(dz, dz);
        sacc += (double)__fmul_rn(dw, dw);
    }
    dred[tid] = sacc;
    __syncthreads();
    for (int stride = 128; stride > 0; stride >>= 1) {
        if (tid < stride) dred[tid] += dred[tid + stride];
        __syncthreads();
    }
    if (tid == 0) g_partial[blockIdx.x] = dred[0];
}

// ---------------------------------------------------------------------------
// finalize (parallel, deterministic fixed-tree reductions in double).
// ---------------------------------------------------------------------------
__global__ void __launch_bounds__(256) vq_finalize(float* __restrict__ out) {
    __shared__ double dr[256];
    __shared__ double hr[256];
    __shared__ int    cr[256];
    const int tid = threadIdx.x;

    double s = 0.0;
    #pragma unroll
    for (int q = 0; q < 4; q++) s += g_partial[tid * 4 + q];
    dr[tid] = s;

    int c = 0;
    #pragma unroll
    for (int q = 0; q < 4; q++) c += g_counts[tid * 4 + q];
    cr[tid] = c;
    __syncthreads();
    for (int st = 128; st > 0; st >>= 1) {
        if (tid < st) { dr[tid] += dr[tid + st]; cr[tid] += cr[tid + st]; }
        __syncthreads();
    }
    float denom = __fadd_rn((float)cr[0], EPS_F);

    double h = 0.0;
    #pragma unroll
    for (int q = 0; q < 4; q++) {
        float p = __fdiv_rn((float)g_counts[tid * 4 + q], denom);
        h += (double)__fmul_rn(p, __logf(__fadd_rn(p, EPS_F)));
    }
    hr[tid] = h;
    __syncthreads();
    for (int st = 128; st > 0; st >>= 1) {
        if (tid < st) hr[tid] += hr[tid + st];
        __syncthreads();
    }

    if (tid == 0) {
        float L = (float)(dr[0] / (double)Z_ELEMS);
        out[Z_ELEMS + 0] = L;                                 // commitment
        out[Z_ELEMS + 1] = L;                                 // codebook
        out[Z_ELEMS + 2] = __fadd_rn(L, __fmul_rn(BETA, L));  // cluster
        out[Z_ELEMS + 3] = __expf(-(float)hr[0]);             // perplexity
    }
}

// ---------------------------------------------------------------------------
extern "C" void kernel_launch(void* const* d_in, const int* in_sizes, int n_in,
                              void* d_out, int out_size) {
    const float* z  = (const float*)d_in[0];   // [65536, 256]
    const float* cb = (const float*)d_in[1];   // [1024, 256]
    float* out = (float*)d_out;

    cudaFuncSetAttribute(vq_argmin, cudaFuncAttributeMaxDynamicSharedMemorySize,
                         SMEM_BYTES);

    vq_init_kernel<<<4, 256>>>();
    vq_prep_cb_kernel<<<KCODES / 32, 256>>>(cb);
    vq_prep_z2_kernel<<<TOKENS / 32, 256>>>(z);
    vq_argmin<<<NBLK_A, 256, SMEM_BYTES>>>(z, cb, out);
    vq_finalize<<<1, 256>>>(out);
}